// round 3
// baseline (speedup 1.0000x reference)
#include <cuda_runtime.h>
#include <cstdint>
#include <math.h>

#define EMAX   250000
#define DEDGE  128
#define DTRI   64

static __device__ __align__(16) float g_R  [EMAX * DEDGE];
static __device__ __align__(16) float g_M1 [EMAX * DEDGE];
static __device__ __align__(16) float g_T  [EMAX * DTRI];
static __device__ __align__(16) float g_X  [EMAX * DTRI];
static __device__ __align__(16) float g_Y  [EMAX * DEDGE];
static __device__ __align__(16) float g_XST[EMAX * DEDGE];
static __device__ __align__(16) float g_Z  [EMAX * DEDGE];

#define INV_SQRT_2  0.70710678118654752440f
#define INV_SQRT_NB 0.35355339059327376220f

__device__ __forceinline__ float silu_f(float x) {
    return x / (1.0f + __expf(-x));
}

// tf32 hi/lo split for 3xTF32 error compensation
__device__ __forceinline__ void split_tf32(float a, uint32_t& hi, uint32_t& lo) {
    uint32_t h;
    asm("cvt.rna.tf32.f32 %0, %1;" : "=r"(h) : "f"(a));
    float l = a - __uint_as_float(h);
    asm("cvt.rna.tf32.f32 %0, %1;" : "=r"(lo) : "f"(l));
    hi = h;
}

__device__ __forceinline__ void mma_tf32(float* c, uint32_t a0, uint32_t a1,
                                         uint32_t a2, uint32_t a3,
                                         uint32_t b0, uint32_t b1) {
    asm volatile(
        "mma.sync.aligned.m16n8k8.row.col.f32.tf32.tf32.f32 "
        "{%0,%1,%2,%3}, {%4,%5,%6,%7}, {%8,%9}, {%0,%1,%2,%3};"
        : "+f"(c[0]), "+f"(c[1]), "+f"(c[2]), "+f"(c[3])
        : "r"(a0), "r"(a1), "r"(a2), "r"(a3), "r"(b0), "r"(b1));
}

#define EPI_NONE 0
#define EPI_SILU 1
#define EPI_SILU_MUL 2

// C[M x N] = epi( A[M x K] @ W[K x N] ), 3xTF32 via mma.sync.
// 256 threads = 8 warps (4 x 2), block tile 128 x N, warp tile 32 x N/2.
// K chunked by 32. smem row stride 36 (conflict-free fragment LDS).
template<int K, int N, int EPI>
__global__ void __launch_bounds__(256)
gemm_mma(const float* __restrict__ A, const float* __restrict__ W,
         const float* __restrict__ Rm, float* __restrict__ out, int M)
{
    constexpr int NT  = N / 16;           // n-tiles (8 wide) per warp
    constexpr int NCH = (K + 31) / 32;
    constexpr int NF4 = N / 4;

    extern __shared__ uint32_t sm[];
    uint32_t* Ah = sm;                    // [128][36]
    uint32_t* Al = Ah + 128 * 36;
    uint32_t* Bh = Al + 128 * 36;         // [N][36]  (Bs[n][k])
    uint32_t* Bl = Bh + N * 36;

    const int tid  = threadIdx.x;
    const int warp = tid >> 5, lane = tid & 31;
    const int g = lane >> 2, t = lane & 3;
    const int warpM = warp & 3, warpN = warp >> 2;
    const int m0 = warpM * 32;
    const int n0 = warpN * (N / 2);
    const int blockRow = blockIdx.x * 128;

    float acc[2][NT][4];
    #pragma unroll
    for (int mt = 0; mt < 2; mt++)
        #pragma unroll
        for (int nt = 0; nt < NT; nt++)
            #pragma unroll
            for (int j = 0; j < 4; j++) acc[mt][nt][j] = 0.0f;

    for (int kb = 0; kb < NCH; kb++) {
        // ---- A chunk: 128 rows x 32 cols, split hi/lo ----
        #pragma unroll
        for (int i = 0; i < 4; i++) {
            int f = tid + i * 256;        // float4 index (128 rows x 8)
            int row = f >> 3, kq = f & 7;
            int grow = blockRow + row;
            int kg = kb * 32 + kq * 4;
            float4 v = make_float4(0.f, 0.f, 0.f, 0.f);
            if (grow < M && kg < K) v = *(const float4*)(A + (size_t)grow * K + kg);
            uint32_t h0, l0, h1, l1, h2, l2, h3, l3;
            split_tf32(v.x, h0, l0); split_tf32(v.y, h1, l1);
            split_tf32(v.z, h2, l2); split_tf32(v.w, h3, l3);
            int base = row * 36 + kq * 4;
            Ah[base + 0] = h0; Ah[base + 1] = h1; Ah[base + 2] = h2; Ah[base + 3] = h3;
            Al[base + 0] = l0; Al[base + 1] = l1; Al[base + 2] = l2; Al[base + 3] = l3;
        }
        // ---- B chunk: 32 rows x N cols, stored transposed Bs[n][k] ----
        #pragma unroll
        for (int i = 0; i < (32 * NF4) / 256; i++) {
            int f = tid + i * 256;
            int k = f / NF4, ng = f % NF4;
            int kg = kb * 32 + k;
            float4 w = make_float4(0.f, 0.f, 0.f, 0.f);
            if (kg < K) w = *(const float4*)(W + (size_t)kg * N + ng * 4);
            float wv[4] = {w.x, w.y, w.z, w.w};
            #pragma unroll
            for (int j = 0; j < 4; j++) {
                uint32_t hi, lo;
                split_tf32(wv[j], hi, lo);
                Bh[(ng * 4 + j) * 36 + k] = hi;
                Bl[(ng * 4 + j) * 36 + k] = lo;
            }
        }
        __syncthreads();

        #pragma unroll
        for (int ks = 0; ks < 4; ks++) {
            uint32_t ah[2][4], al[2][4];
            #pragma unroll
            for (int mt = 0; mt < 2; mt++) {
                int r = (m0 + mt * 16 + g) * 36 + ks * 8;
                ah[mt][0] = Ah[r + t];           al[mt][0] = Al[r + t];
                ah[mt][1] = Ah[r + 288 + t];     al[mt][1] = Al[r + 288 + t];
                ah[mt][2] = Ah[r + t + 4];       al[mt][2] = Al[r + t + 4];
                ah[mt][3] = Ah[r + 288 + t + 4]; al[mt][3] = Al[r + 288 + t + 4];
            }
            #pragma unroll
            for (int nt = 0; nt < NT; nt++) {
                int bbase = (n0 + nt * 8 + g) * 36 + ks * 8 + t;
                uint32_t bh0 = Bh[bbase], bh1 = Bh[bbase + 4];
                uint32_t bl0 = Bl[bbase], bl1 = Bl[bbase + 4];
                #pragma unroll
                for (int mt = 0; mt < 2; mt++) {
                    mma_tf32(acc[mt][nt], ah[mt][0], ah[mt][1], ah[mt][2], ah[mt][3], bh0, bh1);
                    mma_tf32(acc[mt][nt], ah[mt][0], ah[mt][1], ah[mt][2], ah[mt][3], bl0, bl1);
                    mma_tf32(acc[mt][nt], al[mt][0], al[mt][1], al[mt][2], al[mt][3], bh0, bh1);
                }
            }
        }
        __syncthreads();
    }

    // ---- Epilogue ----
    #pragma unroll
    for (int mt = 0; mt < 2; mt++) {
        int r0 = blockRow + m0 + mt * 16 + g;
        #pragma unroll
        for (int half = 0; half < 2; half++) {
            int r = r0 + half * 8;
            if (r >= M) continue;
            #pragma unroll
            for (int nt = 0; nt < NT; nt++) {
                int cc = n0 + nt * 8 + 2 * t;
                float v0 = acc[mt][nt][half * 2 + 0];
                float v1 = acc[mt][nt][half * 2 + 1];
                if (EPI == EPI_SILU || EPI == EPI_SILU_MUL) {
                    v0 = silu_f(v0); v1 = silu_f(v1);
                }
                if (EPI == EPI_SILU_MUL) {
                    float2 rm = *(const float2*)(Rm + (size_t)r * N + cc);
                    v0 *= rm.x; v1 *= rm.y;
                }
                float2 o; o.x = v0; o.y = v1;
                *(float2*)(out + (size_t)r * N + cc) = o;
            }
        }
    }
}

// Triplet gather: X[e][:] = INV_SQRT_NB * sum_nb T[b1[e,nb]][:] * (cbf[e,nb,:] @ W_cbf)
__global__ void __launch_bounds__(256)
triplet_kernel(const float* __restrict__ T, const float* __restrict__ cbf,
               const int* __restrict__ idx_s, const int* __restrict__ basis,
               const float* __restrict__ Wc, float* __restrict__ X, int E)
{
    __shared__ float cb[8][128];
    const int warp = threadIdx.x >> 5;
    const int lane = threadIdx.x & 31;

    float w0[16], w1[16];
    #pragma unroll
    for (int c = 0; c < 16; c++) {
        w0[c] = Wc[c * 64 + lane];
        w1[c] = Wc[c * 64 + 32 + lane];
    }

    const int gw = blockIdx.x * 8 + warp;
    const int nwarps = gridDim.x * 8;

    for (int e = gw; e < E; e += nwarps) {
        int s = idx_s[e];
        int b1v = 0;
        if (lane < 8) b1v = basis[s * 8 + lane];

        float4 v = *(const float4*)(cbf + (size_t)e * 128 + lane * 4);
        *(float4*)(&cb[warp][lane * 4]) = v;
        __syncwarp();

        int bidx[8];
        #pragma unroll
        for (int nb = 0; nb < 8; nb++)
            bidx[nb] = __shfl_sync(0xffffffffu, b1v, nb);

        float t0[8], t1[8];
        #pragma unroll
        for (int nb = 0; nb < 8; nb++) {
            t0[nb] = T[(size_t)bidx[nb] * 64 + lane];
            t1[nb] = T[(size_t)bidx[nb] * 64 + 32 + lane];
        }

        float acc0 = 0.f, acc1 = 0.f;
        #pragma unroll
        for (int nb = 0; nb < 8; nb++) {
            float d0 = 0.f, d1 = 0.f;
            #pragma unroll
            for (int c = 0; c < 16; c++) {
                float a = cb[warp][nb * 16 + c];
                d0 = fmaf(a, w0[c], d0);
                d1 = fmaf(a, w1[c], d1);
            }
            acc0 = fmaf(t0[nb], d0, acc0);
            acc1 = fmaf(t1[nb], d1, acc1);
        }
        X[(size_t)e * 64 + lane]      = acc0 * INV_SQRT_NB;
        X[(size_t)e * 64 + 32 + lane] = acc1 * INV_SQRT_NB;
        __syncwarp();
    }
}

// out[e][:] = (XST[e][:] + Z[idx_swap[e]][:]) * INV_SQRT_2
__global__ void __launch_bounds__(256)
final_kernel(const float* __restrict__ XST, const float* __restrict__ Z,
             const int* __restrict__ swp, float* __restrict__ out, int E)
{
    size_t total = (size_t)E * 32;
    size_t stride = (size_t)gridDim.x * blockDim.x;
    for (size_t i = (size_t)blockIdx.x * blockDim.x + threadIdx.x; i < total; i += stride) {
        size_t e = i >> 5;
        int    q = (int)(i & 31);
        int    s = swp[e];
        float4 a = ((const float4*)XST)[i];
        float4 b = ((const float4*)Z)[(size_t)s * 32 + q];
        float4 r;
        r.x = (a.x + b.x) * INV_SQRT_2;
        r.y = (a.y + b.y) * INV_SQRT_2;
        r.z = (a.z + b.z) * INV_SQRT_2;
        r.w = (a.w + b.w) * INV_SQRT_2;
        ((float4*)out)[i] = r;
    }
}

extern "C" void kernel_launch(void* const* d_in, const int* in_sizes, int n_in,
                              void* d_out, int out_size)
{
    const float* m_st     = (const float*)d_in[0];
    const float* rbf      = (const float*)d_in[1];
    const float* cbf      = (const float*)d_in[2];
    const int*   idx_s    = (const int*)d_in[3];
    const int*   idx_swap = (const int*)d_in[4];
    const int*   basis    = (const int*)d_in[5];
    const float* W_m_rbf  = (const float*)d_in[6];
    const float* W_rbf    = (const float*)d_in[7];
    const float* W_m_cbf  = (const float*)d_in[8];
    const float* W_cbf    = (const float*)d_in[9];
    const float* W_dir    = (const float*)d_in[10];
    const float* W_st     = (const float*)d_in[11];
    const float* W_ts     = (const float*)d_in[12];
    float* out = (float*)d_out;

    const int E = in_sizes[0] / DEDGE;

    float *pR, *pM1, *pT, *pX, *pY, *pXST, *pZ;
    cudaGetSymbolAddress((void**)&pR,   g_R);
    cudaGetSymbolAddress((void**)&pM1,  g_M1);
    cudaGetSymbolAddress((void**)&pT,   g_T);
    cudaGetSymbolAddress((void**)&pX,   g_X);
    cudaGetSymbolAddress((void**)&pY,   g_Y);
    cudaGetSymbolAddress((void**)&pXST, g_XST);
    cudaGetSymbolAddress((void**)&pZ,   g_Z);

    const int gB = (E + 127) / 128;

    // smem bytes: 2*128*36 (A hi/lo) + 2*N*36 (B hi/lo), 4B each
    const int smem_n128 = (2 * 128 * 36 + 2 * 128 * 36) * 4;  // 73728
    const int smem_n64  = (2 * 128 * 36 + 2 * 64  * 36) * 4;  // 55296

    cudaFuncSetAttribute(gemm_mma<16, 128, EPI_NONE>,
                         cudaFuncAttributeMaxDynamicSharedMemorySize, smem_n128);
    cudaFuncSetAttribute(gemm_mma<128, 128, EPI_SILU_MUL>,
                         cudaFuncAttributeMaxDynamicSharedMemorySize, smem_n128);
    cudaFuncSetAttribute(gemm_mma<128, 64, EPI_SILU>,
                         cudaFuncAttributeMaxDynamicSharedMemorySize, smem_n64);
    cudaFuncSetAttribute(gemm_mma<64, 128, EPI_SILU>,
                         cudaFuncAttributeMaxDynamicSharedMemorySize, smem_n128);
    cudaFuncSetAttribute(gemm_mma<128, 128, EPI_SILU>,
                         cudaFuncAttributeMaxDynamicSharedMemorySize, smem_n128);

    // K0: R = rbf @ W_rbf
    gemm_mma<16, 128, EPI_NONE><<<gB, 256, smem_n128>>>(rbf, W_rbf, nullptr, pR, E);
    // K1: M1 = silu(m_st @ W_m_rbf) * R
    gemm_mma<128, 128, EPI_SILU_MUL><<<gB, 256, smem_n128>>>(m_st, W_m_rbf, pR, pM1, E);
    // K2: T = silu(M1 @ W_m_cbf)
    gemm_mma<128, 64, EPI_SILU><<<gB, 256, smem_n64>>>(pM1, W_m_cbf, nullptr, pT, E);
    // K3: triplet gather -> X
    triplet_kernel<<<2048, 256>>>(pT, cbf, idx_s, basis, W_cbf, pX, E);
    // K4: Y = silu(X @ W_dir)
    gemm_mma<64, 128, EPI_SILU><<<gB, 256, smem_n128>>>(pX, W_dir, nullptr, pY, E);
    // K5a: XST = silu(Y @ W_st)
    gemm_mma<128, 128, EPI_SILU><<<gB, 256, smem_n128>>>(pY, W_st, nullptr, pXST, E);
    // K5b: Z = silu(Y @ W_ts)
    gemm_mma<128, 128, EPI_SILU><<<gB, 256, smem_n128>>>(pY, W_ts, nullptr, pZ, E);
    // K6: out = (XST + Z[idx_swap]) * INV_SQRT_2
    final_kernel<<<4096, 256>>>(pXST, pZ, idx_swap, out, E);
}

// round 4
// speedup vs baseline: 1.1315x; 1.1315x over previous
#include <cuda_runtime.h>
#include <cuda_bf16.h>
#include <cstdint>
#include <math.h>

#define EMAX   250000
#define DEDGE  128
#define DTRI   64

static __device__ __align__(16) float g_R  [EMAX * DEDGE];
static __device__ __align__(16) float g_M1 [EMAX * DEDGE];
static __device__ __align__(16) float g_T  [EMAX * DTRI];
static __device__ __align__(16) float g_X  [EMAX * DTRI];
static __device__ __align__(16) float g_Y  [EMAX * DEDGE];
static __device__ __align__(16) float g_XST[EMAX * DEDGE];
static __device__ __align__(16) float g_Z  [EMAX * DEDGE];

#define INV_SQRT_2  0.70710678118654752440f
#define INV_SQRT_NB 0.35355339059327376220f

__device__ __forceinline__ float silu_f(float x) {
    return x / (1.0f + __expf(-x));
}

__device__ __forceinline__ uint32_t smem_u32(const void* p) {
    uint32_t a;
    asm("{ .reg .u64 t; cvta.to.shared.u64 t, %1; cvt.u32.u64 %0, t; }" : "=r"(a) : "l"(p));
    return a;
}

// Split (x, y) into bf16 hi pair and bf16 lo (residual) pair, packed 2x16b.
__device__ __forceinline__ void split_pair(float x, float y, uint32_t& hi, uint32_t& lo) {
    __nv_bfloat16 hx = __float2bfloat16(x);
    __nv_bfloat16 hy = __float2bfloat16(y);
    __nv_bfloat16 lx = __float2bfloat16(x - __bfloat162float(hx));
    __nv_bfloat16 ly = __float2bfloat16(y - __bfloat162float(hy));
    __nv_bfloat162 H; H.x = hx; H.y = hy;
    __nv_bfloat162 L; L.x = lx; L.y = ly;
    hi = *(uint32_t*)&H;
    lo = *(uint32_t*)&L;
}

__device__ __forceinline__ void ldsm4(uint32_t addr, uint32_t& r0, uint32_t& r1,
                                      uint32_t& r2, uint32_t& r3) {
    asm volatile("ldmatrix.sync.aligned.m8n8.x4.shared.b16 {%0,%1,%2,%3}, [%4];"
                 : "=r"(r0), "=r"(r1), "=r"(r2), "=r"(r3) : "r"(addr));
}

__device__ __forceinline__ void mma_bf16(float* c, const uint32_t* a,
                                         uint32_t b0, uint32_t b1) {
    asm volatile(
        "mma.sync.aligned.m16n8k16.row.col.f32.bf16.bf16.f32 "
        "{%0,%1,%2,%3}, {%4,%5,%6,%7}, {%8,%9}, {%0,%1,%2,%3};"
        : "+f"(c[0]), "+f"(c[1]), "+f"(c[2]), "+f"(c[3])
        : "r"(a[0]), "r"(a[1]), "r"(a[2]), "r"(a[3]), "r"(b0), "r"(b1));
}

#define EPI_NONE 0
#define EPI_SILU 1
#define EPI_SILU_MUL 2

// C[M x N] = epi( A[M x K] @ W[K x N] ), bf16 split-3 via mma.sync m16n8k16.
// 256 threads = 8 warps (4 x 2): block tile 128 x N, warp tile 32 x N/2.
// K chunked by 32. smem row stride 40 b16 (80 B) -> conflict-free ldmatrix.
template<int K, int N, int EPI>
__global__ void __launch_bounds__(256)
gemm_bf16(const float* __restrict__ A, const float* __restrict__ W,
          const float* __restrict__ Rm, float* __restrict__ out, int M)
{
    constexpr int NT    = N / 16;    // n8-tiles per warp (warp covers N/2)
    constexpr int NPAIR = NT / 2;
    constexpr int NCH   = (K + 31) / 32;
    constexpr int NF4   = N / 4;
    constexpr int ST    = 40;        // b16 stride per row

    __shared__ __align__(16) uint16_t smu[2 * 128 * ST + 2 * 128 * ST];
    // layout (b16 units): Ah[128*ST] | Al[128*ST] | Bh[N*ST] | Bl[N*ST]
    constexpr uint32_t OFF_AL_B = 128 * ST * 2;           // byte offsets
    constexpr uint32_t OFF_BH_B = 2 * 128 * ST * 2;
    constexpr uint32_t OFF_BL_B = OFF_BH_B + N * ST * 2;

    const uint32_t sbase = smem_u32(smu);

    const int tid  = threadIdx.x;
    const int warp = tid >> 5, lane = tid & 31;
    const int g = lane >> 2, t = lane & 3;
    const int warpM = warp & 3, warpN = warp >> 2;
    const int m0 = warpM * 32;
    const int n0 = warpN * (N / 2);
    const int blockRow = blockIdx.x * 128;

    // ldmatrix per-lane row/col (invariant parts)
    const int lr = lane & 7;
    const int rowA_base = m0 + lr + ((lane >> 3) & 1) * 8;
    const int kA_off    = (lane >> 4) * 8;
    const int rowB_base = n0 + lr + (lane >> 4) * 8;
    const int kB_off    = ((lane >> 3) & 1) * 8;

    float acc[2][NT][4];
    #pragma unroll
    for (int mt = 0; mt < 2; mt++)
        #pragma unroll
        for (int nt = 0; nt < NT; nt++)
            #pragma unroll
            for (int j = 0; j < 4; j++) acc[mt][nt][j] = 0.0f;

    for (int kb = 0; kb < NCH; kb++) {
        // ---- A chunk: 128 rows x 32 floats -> bf16 hi/lo ----
        #pragma unroll
        for (int i = 0; i < 4; i++) {
            int f = tid + i * 256;            // float4 slot: 128 rows x 8
            int row = f >> 3, kq = f & 7;
            int grow = blockRow + row;
            int kg = kb * 32 + kq * 4;
            float4 v = make_float4(0.f, 0.f, 0.f, 0.f);
            if (grow < M && kg < K) v = *(const float4*)(A + (size_t)grow * K + kg);
            uint32_t h0, l0, h1, l1;
            split_pair(v.x, v.y, h0, l0);
            split_pair(v.z, v.w, h1, l1);
            int base = row * ST + kq * 4;     // b16 units (even)
            *(uint32_t*)((char*)smu + base * 2)                = h0;
            *(uint32_t*)((char*)smu + base * 2 + 4)            = h1;
            *(uint32_t*)((char*)smu + OFF_AL_B + base * 2)     = l0;
            *(uint32_t*)((char*)smu + OFF_AL_B + base * 2 + 4) = l1;
        }
        // ---- B chunk: 32 k-rows x N cols -> transposed Bs[n][k], hi/lo ----
        #pragma unroll
        for (int i = 0; i < (32 * NF4) / 256; i++) {
            int f = tid + i * 256;
            int k = f / NF4, ng = f % NF4;
            int kg = kb * 32 + k;
            float4 w = make_float4(0.f, 0.f, 0.f, 0.f);
            if (kg < K) w = *(const float4*)(W + (size_t)kg * N + ng * 4);
            float wv[4] = {w.x, w.y, w.z, w.w};
            #pragma unroll
            for (int j = 0; j < 4; j++) {
                __nv_bfloat16 hi = __float2bfloat16(wv[j]);
                __nv_bfloat16 lo = __float2bfloat16(wv[j] - __bfloat162float(hi));
                int e = (ng * 4 + j) * ST + k;
                *(uint16_t*)((char*)smu + OFF_BH_B + e * 2) = *(uint16_t*)&hi;
                *(uint16_t*)((char*)smu + OFF_BL_B + e * 2) = *(uint16_t*)&lo;
            }
        }
        __syncthreads();

        #pragma unroll
        for (int ks = 0; ks < 2; ks++) {
            uint32_t ah[2][4], al[2][4];
            #pragma unroll
            for (int mt = 0; mt < 2; mt++) {
                uint32_t ea = ((rowA_base + mt * 16) * ST + ks * 16 + kA_off) * 2;
                ldsm4(sbase + ea,            ah[mt][0], ah[mt][1], ah[mt][2], ah[mt][3]);
                ldsm4(sbase + OFF_AL_B + ea, al[mt][0], al[mt][1], al[mt][2], al[mt][3]);
            }
            #pragma unroll
            for (int p = 0; p < NPAIR; p++) {
                uint32_t eb = ((rowB_base + p * 16) * ST + ks * 16 + kB_off) * 2;
                uint32_t bh0, bh1, bh2, bh3, bl0, bl1, bl2, bl3;
                ldsm4(sbase + OFF_BH_B + eb, bh0, bh1, bh2, bh3);
                ldsm4(sbase + OFF_BL_B + eb, bl0, bl1, bl2, bl3);
                #pragma unroll
                for (int mt = 0; mt < 2; mt++) {
                    float* c0 = acc[mt][2 * p];
                    float* c1 = acc[mt][2 * p + 1];
                    mma_bf16(c0, ah[mt], bh0, bh1);
                    mma_bf16(c0, ah[mt], bl0, bl1);
                    mma_bf16(c0, al[mt], bh0, bh1);
                    mma_bf16(c1, ah[mt], bh2, bh3);
                    mma_bf16(c1, ah[mt], bl2, bl3);
                    mma_bf16(c1, al[mt], bh2, bh3);
                }
            }
        }
        __syncthreads();
    }

    // ---- Epilogue ----
    #pragma unroll
    for (int mt = 0; mt < 2; mt++) {
        int r0 = blockRow + m0 + mt * 16 + g;
        #pragma unroll
        for (int half = 0; half < 2; half++) {
            int r = r0 + half * 8;
            if (r >= M) continue;
            #pragma unroll
            for (int nt = 0; nt < NT; nt++) {
                int cc = n0 + nt * 8 + 2 * t;
                float v0 = acc[mt][nt][half * 2 + 0];
                float v1 = acc[mt][nt][half * 2 + 1];
                if (EPI == EPI_SILU || EPI == EPI_SILU_MUL) {
                    v0 = silu_f(v0); v1 = silu_f(v1);
                }
                if (EPI == EPI_SILU_MUL) {
                    float2 rm = *(const float2*)(Rm + (size_t)r * N + cc);
                    v0 *= rm.x; v1 *= rm.y;
                }
                float2 o; o.x = v0; o.y = v1;
                *(float2*)(out + (size_t)r * N + cc) = o;
            }
        }
    }
}

// Triplet gather: X[e][:] = INV_SQRT_NB * sum_nb T[b1[e,nb]][:] * (cbf[e,nb,:] @ W_cbf)
__global__ void __launch_bounds__(256)
triplet_kernel(const float* __restrict__ T, const float* __restrict__ cbf,
               const int* __restrict__ idx_s, const int* __restrict__ basis,
               const float* __restrict__ Wc, float* __restrict__ X, int E)
{
    __shared__ float cb[8][128];
    const int warp = threadIdx.x >> 5;
    const int lane = threadIdx.x & 31;

    float w0[16], w1[16];
    #pragma unroll
    for (int c = 0; c < 16; c++) {
        w0[c] = Wc[c * 64 + lane];
        w1[c] = Wc[c * 64 + 32 + lane];
    }

    const int gw = blockIdx.x * 8 + warp;
    const int nwarps = gridDim.x * 8;

    for (int e = gw; e < E; e += nwarps) {
        int s = idx_s[e];
        int b1v = 0;
        if (lane < 8) b1v = basis[s * 8 + lane];

        float4 v = *(const float4*)(cbf + (size_t)e * 128 + lane * 4);
        *(float4*)(&cb[warp][lane * 4]) = v;
        __syncwarp();

        int bidx[8];
        #pragma unroll
        for (int nb = 0; nb < 8; nb++)
            bidx[nb] = __shfl_sync(0xffffffffu, b1v, nb);

        float t0[8], t1[8];
        #pragma unroll
        for (int nb = 0; nb < 8; nb++) {
            t0[nb] = T[(size_t)bidx[nb] * 64 + lane];
            t1[nb] = T[(size_t)bidx[nb] * 64 + 32 + lane];
        }

        float acc0 = 0.f, acc1 = 0.f;
        #pragma unroll
        for (int nb = 0; nb < 8; nb++) {
            float d0 = 0.f, d1 = 0.f;
            #pragma unroll
            for (int c = 0; c < 16; c++) {
                float a = cb[warp][nb * 16 + c];
                d0 = fmaf(a, w0[c], d0);
                d1 = fmaf(a, w1[c], d1);
            }
            acc0 = fmaf(t0[nb], d0, acc0);
            acc1 = fmaf(t1[nb], d1, acc1);
        }
        X[(size_t)e * 64 + lane]      = acc0 * INV_SQRT_NB;
        X[(size_t)e * 64 + 32 + lane] = acc1 * INV_SQRT_NB;
        __syncwarp();
    }
}

// out[e][:] = (XST[e][:] + Z[idx_swap[e]][:]) * INV_SQRT_2
__global__ void __launch_bounds__(256)
final_kernel(const float* __restrict__ XST, const float* __restrict__ Z,
             const int* __restrict__ swp, float* __restrict__ out, int E)
{
    size_t total = (size_t)E * 32;
    size_t stride = (size_t)gridDim.x * blockDim.x;
    for (size_t i = (size_t)blockIdx.x * blockDim.x + threadIdx.x; i < total; i += stride) {
        size_t e = i >> 5;
        int    q = (int)(i & 31);
        int    s = swp[e];
        float4 a = ((const float4*)XST)[i];
        float4 b = ((const float4*)Z)[(size_t)s * 32 + q];
        float4 r;
        r.x = (a.x + b.x) * INV_SQRT_2;
        r.y = (a.y + b.y) * INV_SQRT_2;
        r.z = (a.z + b.z) * INV_SQRT_2;
        r.w = (a.w + b.w) * INV_SQRT_2;
        ((float4*)out)[i] = r;
    }
}

extern "C" void kernel_launch(void* const* d_in, const int* in_sizes, int n_in,
                              void* d_out, int out_size)
{
    const float* m_st     = (const float*)d_in[0];
    const float* rbf      = (const float*)d_in[1];
    const float* cbf      = (const float*)d_in[2];
    const int*   idx_s    = (const int*)d_in[3];
    const int*   idx_swap = (const int*)d_in[4];
    const int*   basis    = (const int*)d_in[5];
    const float* W_m_rbf  = (const float*)d_in[6];
    const float* W_rbf    = (const float*)d_in[7];
    const float* W_m_cbf  = (const float*)d_in[8];
    const float* W_cbf    = (const float*)d_in[9];
    const float* W_dir    = (const float*)d_in[10];
    const float* W_st     = (const float*)d_in[11];
    const float* W_ts     = (const float*)d_in[12];
    float* out = (float*)d_out;

    const int E = in_sizes[0] / DEDGE;

    float *pR, *pM1, *pT, *pX, *pY, *pXST, *pZ;
    cudaGetSymbolAddress((void**)&pR,   g_R);
    cudaGetSymbolAddress((void**)&pM1,  g_M1);
    cudaGetSymbolAddress((void**)&pT,   g_T);
    cudaGetSymbolAddress((void**)&pX,   g_X);
    cudaGetSymbolAddress((void**)&pY,   g_Y);
    cudaGetSymbolAddress((void**)&pXST, g_XST);
    cudaGetSymbolAddress((void**)&pZ,   g_Z);

    const int gB = (E + 127) / 128;

    // K0: R = rbf @ W_rbf
    gemm_bf16<16, 128, EPI_NONE><<<gB, 256>>>(rbf, W_rbf, nullptr, pR, E);
    // K1: M1 = silu(m_st @ W_m_rbf) * R
    gemm_bf16<128, 128, EPI_SILU_MUL><<<gB, 256>>>(m_st, W_m_rbf, pR, pM1, E);
    // K2: T = silu(M1 @ W_m_cbf)
    gemm_bf16<128, 64, EPI_SILU><<<gB, 256>>>(pM1, W_m_cbf, nullptr, pT, E);
    // K3: triplet gather -> X
    triplet_kernel<<<2048, 256>>>(pT, cbf, idx_s, basis, W_cbf, pX, E);
    // K4: Y = silu(X @ W_dir)
    gemm_bf16<64, 128, EPI_SILU><<<gB, 256>>>(pX, W_dir, nullptr, pY, E);
    // K5a: XST = silu(Y @ W_st)
    gemm_bf16<128, 128, EPI_SILU><<<gB, 256>>>(pY, W_st, nullptr, pXST, E);
    // K5b: Z = silu(Y @ W_ts)
    gemm_bf16<128, 128, EPI_SILU><<<gB, 256>>>(pY, W_ts, nullptr, pZ, E);
    // K6: out = (XST + Z[idx_swap]) * INV_SQRT_2
    final_kernel<<<4096, 256>>>(pXST, pZ, idx_swap, out, E);
}

// round 5
// speedup vs baseline: 1.6330x; 1.4432x over previous
#include <cuda_runtime.h>
#include <cuda_bf16.h>
#include <cstdint>
#include <math.h>

#define EMAX   250000
#define DEDGE  128
#define DTRI   64

// fp32 intermediates
static __device__ __align__(16) float g_R  [EMAX * DEDGE];
static __device__ __align__(16) float g_T  [EMAX * DTRI];
static __device__ __align__(16) float g_XST[EMAX * DEDGE];
static __device__ __align__(16) float g_Z  [EMAX * DEDGE];
// bf16 hi/lo pre-split activations
static __device__ __align__(16) __nv_bfloat16 g_msth[EMAX * DEDGE];
static __device__ __align__(16) __nv_bfloat16 g_mstl[EMAX * DEDGE];
static __device__ __align__(16) __nv_bfloat16 g_rbfh[EMAX * 16];
static __device__ __align__(16) __nv_bfloat16 g_rbfl[EMAX * 16];
static __device__ __align__(16) __nv_bfloat16 g_M1h [EMAX * DEDGE];
static __device__ __align__(16) __nv_bfloat16 g_M1l [EMAX * DEDGE];
static __device__ __align__(16) __nv_bfloat16 g_Xh  [EMAX * DTRI];
static __device__ __align__(16) __nv_bfloat16 g_Xl  [EMAX * DTRI];
static __device__ __align__(16) __nv_bfloat16 g_Yh  [EMAX * DEDGE];
static __device__ __align__(16) __nv_bfloat16 g_Yl  [EMAX * DEDGE];
// bf16 hi/lo transposed weights [N][K]
static __device__ __align__(16) __nv_bfloat16 g_Wrbh [128 * 16],  g_Wrbl [128 * 16];
static __device__ __align__(16) __nv_bfloat16 g_Wmrh [128 * 128], g_Wmrl [128 * 128];
static __device__ __align__(16) __nv_bfloat16 g_Wmch [64 * 128],  g_Wmcl [64 * 128];
static __device__ __align__(16) __nv_bfloat16 g_Wdh  [128 * 64],  g_Wdl  [128 * 64];
static __device__ __align__(16) __nv_bfloat16 g_Wsth [128 * 128], g_Wstl [128 * 128];
static __device__ __align__(16) __nv_bfloat16 g_Wtsh [128 * 128], g_Wtsl [128 * 128];

#define INV_SQRT_2  0.70710678118654752440f
#define INV_SQRT_NB 0.35355339059327376220f

__device__ __forceinline__ float silu_f(float x) {
    return x / (1.0f + __expf(-x));
}
__device__ __forceinline__ uint32_t smem_u32(const void* p) {
    uint32_t a;
    asm("{ .reg .u64 t; cvta.to.shared.u64 t, %1; cvt.u32.u64 %0, t; }" : "=r"(a) : "l"(p));
    return a;
}
__device__ __forceinline__ void cp_async16(uint32_t dst, const void* src, bool v) {
    int sz = v ? 16 : 0;
    asm volatile("cp.async.cg.shared.global [%0], [%1], 16, %2;"
                 :: "r"(dst), "l"(src), "r"(sz));
}
#define CP_COMMIT() asm volatile("cp.async.commit_group;" ::: "memory")
template<int n> __device__ __forceinline__ void cp_wait() {
    asm volatile("cp.async.wait_group %0;" :: "n"(n) : "memory");
}
__device__ __forceinline__ void ldsm4(uint32_t addr, uint32_t& r0, uint32_t& r1,
                                      uint32_t& r2, uint32_t& r3) {
    asm volatile("ldmatrix.sync.aligned.m8n8.x4.shared.b16 {%0,%1,%2,%3}, [%4];"
                 : "=r"(r0), "=r"(r1), "=r"(r2), "=r"(r3) : "r"(addr));
}
__device__ __forceinline__ void mma_bf16(float* c, const uint32_t* a,
                                         uint32_t b0, uint32_t b1) {
    asm volatile(
        "mma.sync.aligned.m16n8k16.row.col.f32.bf16.bf16.f32 "
        "{%0,%1,%2,%3}, {%4,%5,%6,%7}, {%8,%9}, {%0,%1,%2,%3};"
        : "+f"(c[0]), "+f"(c[1]), "+f"(c[2]), "+f"(c[3])
        : "r"(a[0]), "r"(a[1]), "r"(a[2]), "r"(a[3]), "r"(b0), "r"(b1));
}
__device__ __forceinline__ void split1(float v, __nv_bfloat16& h, __nv_bfloat16& l) {
    h = __float2bfloat16(v);
    l = __float2bfloat16(v - __bfloat162float(h));
}

// ---------------- setup split kernels ----------------
__global__ void split_rows(const float* __restrict__ src,
                           __nv_bfloat16* __restrict__ dh,
                           __nv_bfloat16* __restrict__ dl, int n2)
{
    int i = blockIdx.x * blockDim.x + threadIdx.x;
    if (i >= n2) return;
    float2 v = ((const float2*)src)[i];
    __nv_bfloat16 hx, lx, hy, ly;
    split1(v.x, hx, lx); split1(v.y, hy, ly);
    __nv_bfloat162 H; H.x = hx; H.y = hy;
    __nv_bfloat162 L; L.x = lx; L.y = ly;
    ((__nv_bfloat162*)dh)[i] = H;
    ((__nv_bfloat162*)dl)[i] = L;
}

// W[K][N] fp32 -> Wt[N][K] bf16 hi/lo
__global__ void split_w_t(const float* __restrict__ src,
                          __nv_bfloat16* __restrict__ dh,
                          __nv_bfloat16* __restrict__ dl, int K, int N)
{
    int i = blockIdx.x * blockDim.x + threadIdx.x;
    if (i >= K * N) return;
    int k = i / N, n = i % N;
    __nv_bfloat16 h, l;
    split1(src[i], h, l);
    dh[n * K + k] = h;
    dl[n * K + k] = l;
}

#define EPI_NONE 0
#define EPI_SILU 1
#define EPI_SILU_MUL 2
#define OUT_F32 0
#define OUT_BF16HL 1

// C = epi(A @ Wt^T), A pre-split bf16 hi/lo [M][K], Wt pre-split bf16 hi/lo [N][K].
// bf16 split-3 mma (ah*bh + ah*bl + al*bh), cp.async double-buffered K chunks of 32.
template<int K, int N, int EPI, int OUT>
__global__ void __launch_bounds__(256)
gemm2(const __nv_bfloat16* __restrict__ Ah, const __nv_bfloat16* __restrict__ Al,
      const __nv_bfloat16* __restrict__ Bh, const __nv_bfloat16* __restrict__ Bl,
      const float* __restrict__ Rm, float* __restrict__ outf,
      __nv_bfloat16* __restrict__ oh, __nv_bfloat16* __restrict__ ol, int M)
{
    constexpr int NT    = N / 16;
    constexpr int NPAIR = NT / 2;
    constexpr int NCH   = (K + 31) / 32;
    constexpr int ST    = 40;                       // b16 stride per row
    constexpr int OFF_AL = 128 * ST;                // b16 offsets within stage
    constexpr int OFF_BH = 2 * 128 * ST;
    constexpr int OFF_BL = 2 * 128 * ST + N * ST;
    constexpr int SSZ    = 2 * 128 * ST + 2 * N * ST;  // b16 per stage

    extern __shared__ __align__(16) uint16_t smu[];
    const uint32_t sbase = smem_u32(smu);

    const int tid  = threadIdx.x;
    const int warp = tid >> 5, lane = tid & 31;
    const int g = lane >> 2, t = lane & 3;
    const int warpM = warp & 3, warpN = warp >> 2;
    const int m0 = warpM * 32;
    const int n0 = warpN * (N / 2);
    const int blockRow = blockIdx.x * 128;

    const int lr = lane & 7;
    const int rowA_base = m0 + lr + ((lane >> 3) & 1) * 8;
    const int kA_off    = (lane >> 4) * 8;
    const int rowB_base = n0 + lr + (lane >> 4) * 8;
    const int kB_off    = ((lane >> 3) & 1) * 8;

    float acc[2][NT][4];
    #pragma unroll
    for (int mt = 0; mt < 2; mt++)
        #pragma unroll
        for (int nt = 0; nt < NT; nt++)
            #pragma unroll
            for (int j = 0; j < 4; j++) acc[mt][nt][j] = 0.0f;

    // ---- chunk loader (cp.async) ----
    auto load_chunk = [&](int kb, int stage) {
        const int k0 = kb * 32;
        const uint32_t sb = sbase + stage * SSZ * 2;
        #pragma unroll
        for (int j = 0; j < 2; j++) {               // A: 512 granules per array
            int gg = tid + j * 256;
            int row = gg >> 2, kq = gg & 3;
            bool v = (blockRow + row < M) && (k0 + kq * 8 < K);
            size_t so = (size_t)(blockRow + row) * K + k0 + kq * 8;
            const __nv_bfloat16* sh = v ? (Ah + so) : Ah;
            const __nv_bfloat16* sl = v ? (Al + so) : Al;
            uint32_t d = sb + (uint32_t)(row * ST + kq * 8) * 2;
            cp_async16(d, sh, v);
            cp_async16(d + OFF_AL * 2, sl, v);
        }
        #pragma unroll
        for (int j = 0; j < (N * 4) / 256; j++) {   // B: N*4 granules per array
            int gg = tid + j * 256;
            int n = gg >> 2, kq = gg & 3;
            bool v = (k0 + kq * 8 < K);
            size_t so = (size_t)n * K + k0 + kq * 8;
            const __nv_bfloat16* sh = v ? (Bh + so) : Bh;
            const __nv_bfloat16* sl = v ? (Bl + so) : Bl;
            uint32_t d = sb + (uint32_t)(OFF_BH + n * ST + kq * 8) * 2;
            cp_async16(d, sh, v);
            cp_async16(d + N * ST * 2, sl, v);
        }
        CP_COMMIT();
    };

    load_chunk(0, 0);

    for (int kb = 0; kb < NCH; kb++) {
        if (kb + 1 < NCH) {
            load_chunk(kb + 1, (kb + 1) & 1);
            cp_wait<1>();
        } else {
            cp_wait<0>();
        }
        __syncthreads();

        const uint32_t sb = sbase + (uint32_t)(kb & 1) * SSZ * 2;
        #pragma unroll
        for (int ks = 0; ks < 2; ks++) {
            uint32_t ah[2][4], al[2][4];
            #pragma unroll
            for (int mt = 0; mt < 2; mt++) {
                uint32_t ea = (uint32_t)((rowA_base + mt * 16) * ST + ks * 16 + kA_off) * 2;
                ldsm4(sb + ea,              ah[mt][0], ah[mt][1], ah[mt][2], ah[mt][3]);
                ldsm4(sb + OFF_AL * 2 + ea, al[mt][0], al[mt][1], al[mt][2], al[mt][3]);
            }
            #pragma unroll
            for (int p = 0; p < NPAIR; p++) {
                uint32_t eb = (uint32_t)((rowB_base + p * 16) * ST + ks * 16 + kB_off) * 2;
                uint32_t bh0, bh1, bh2, bh3, bl0, bl1, bl2, bl3;
                ldsm4(sb + OFF_BH * 2 + eb, bh0, bh1, bh2, bh3);
                ldsm4(sb + OFF_BL * 2 + eb, bl0, bl1, bl2, bl3);
                #pragma unroll
                for (int mt = 0; mt < 2; mt++) {
                    float* c0 = acc[mt][2 * p];
                    float* c1 = acc[mt][2 * p + 1];
                    mma_bf16(c0, ah[mt], bh0, bh1);
                    mma_bf16(c0, ah[mt], bl0, bl1);
                    mma_bf16(c0, al[mt], bh0, bh1);
                    mma_bf16(c1, ah[mt], bh2, bh3);
                    mma_bf16(c1, ah[mt], bl2, bl3);
                    mma_bf16(c1, al[mt], bh2, bh3);
                }
            }
        }
        __syncthreads();
    }

    // ---- epilogue ----
    #pragma unroll
    for (int mt = 0; mt < 2; mt++) {
        int r0 = blockRow + m0 + mt * 16 + g;
        #pragma unroll
        for (int half = 0; half < 2; half++) {
            int r = r0 + half * 8;
            if (r >= M) continue;
            #pragma unroll
            for (int nt = 0; nt < NT; nt++) {
                int cc = n0 + nt * 8 + 2 * t;
                float v0 = acc[mt][nt][half * 2 + 0];
                float v1 = acc[mt][nt][half * 2 + 1];
                if (EPI == EPI_SILU || EPI == EPI_SILU_MUL) {
                    v0 = silu_f(v0); v1 = silu_f(v1);
                }
                if (EPI == EPI_SILU_MUL) {
                    float2 rm = *(const float2*)(Rm + (size_t)r * N + cc);
                    v0 *= rm.x; v1 *= rm.y;
                }
                if (OUT == OUT_F32) {
                    float2 o; o.x = v0; o.y = v1;
                    *(float2*)(outf + (size_t)r * N + cc) = o;
                } else {
                    __nv_bfloat16 h0, l0, h1, l1;
                    split1(v0, h0, l0); split1(v1, h1, l1);
                    __nv_bfloat162 H; H.x = h0; H.y = h1;
                    __nv_bfloat162 L; L.x = l0; L.y = l1;
                    *(__nv_bfloat162*)(oh + (size_t)r * N + cc) = H;
                    *(__nv_bfloat162*)(ol + (size_t)r * N + cc) = L;
                }
            }
        }
    }
}

// Triplet gather: X[e][:] = INV_SQRT_NB * sum_nb T[b1[e,nb]][:] * (cbf[e,nb,:] @ W_cbf)
// Writes X as bf16 hi/lo (feeds next GEMM).
__global__ void __launch_bounds__(256)
triplet_kernel(const float* __restrict__ T, const float* __restrict__ cbf,
               const int* __restrict__ idx_s, const int* __restrict__ basis,
               const float* __restrict__ Wc,
               __nv_bfloat16* __restrict__ Xh, __nv_bfloat16* __restrict__ Xl, int E)
{
    __shared__ float cb[8][128];
    const int warp = threadIdx.x >> 5;
    const int lane = threadIdx.x & 31;

    float w0[16], w1[16];
    #pragma unroll
    for (int c = 0; c < 16; c++) {
        w0[c] = Wc[c * 64 + lane];
        w1[c] = Wc[c * 64 + 32 + lane];
    }

    const int gw = blockIdx.x * 8 + warp;
    const int nwarps = gridDim.x * 8;

    for (int e = gw; e < E; e += nwarps) {
        int s = idx_s[e];
        int b1v = 0;
        if (lane < 8) b1v = basis[s * 8 + lane];

        float4 v = *(const float4*)(cbf + (size_t)e * 128 + lane * 4);
        *(float4*)(&cb[warp][lane * 4]) = v;
        __syncwarp();

        int bidx[8];
        #pragma unroll
        for (int nb = 0; nb < 8; nb++)
            bidx[nb] = __shfl_sync(0xffffffffu, b1v, nb);

        float t0[8], t1[8];
        #pragma unroll
        for (int nb = 0; nb < 8; nb++) {
            t0[nb] = T[(size_t)bidx[nb] * 64 + lane];
            t1[nb] = T[(size_t)bidx[nb] * 64 + 32 + lane];
        }

        float acc0 = 0.f, acc1 = 0.f;
        #pragma unroll
        for (int nb = 0; nb < 8; nb++) {
            float d0 = 0.f, d1 = 0.f;
            #pragma unroll
            for (int c = 0; c < 16; c++) {
                float a = cb[warp][nb * 16 + c];
                d0 = fmaf(a, w0[c], d0);
                d1 = fmaf(a, w1[c], d1);
            }
            acc0 = fmaf(t0[nb], d0, acc0);
            acc1 = fmaf(t1[nb], d1, acc1);
        }
        float x0 = acc0 * INV_SQRT_NB;
        float x1 = acc1 * INV_SQRT_NB;
        __nv_bfloat16 h0, l0, h1, l1;
        split1(x0, h0, l0); split1(x1, h1, l1);
        Xh[(size_t)e * 64 + lane]      = h0;
        Xh[(size_t)e * 64 + 32 + lane] = h1;
        Xl[(size_t)e * 64 + lane]      = l0;
        Xl[(size_t)e * 64 + 32 + lane] = l1;
        __syncwarp();
    }
}

// out[e][:] = (XST[e][:] + Z[idx_swap[e]][:]) * INV_SQRT_2
__global__ void __launch_bounds__(256)
final_kernel(const float* __restrict__ XST, const float* __restrict__ Z,
             const int* __restrict__ swp, float* __restrict__ out, int E)
{
    size_t total = (size_t)E * 32;
    size_t stride = (size_t)gridDim.x * blockDim.x;
    for (size_t i = (size_t)blockIdx.x * blockDim.x + threadIdx.x; i < total; i += stride) {
        size_t e = i >> 5;
        int    q = (int)(i & 31);
        int    s = swp[e];
        float4 a = ((const float4*)XST)[i];
        float4 b = ((const float4*)Z)[(size_t)s * 32 + q];
        float4 r;
        r.x = (a.x + b.x) * INV_SQRT_2;
        r.y = (a.y + b.y) * INV_SQRT_2;
        r.z = (a.z + b.z) * INV_SQRT_2;
        r.w = (a.w + b.w) * INV_SQRT_2;
        ((float4*)out)[i] = r;
    }
}

extern "C" void kernel_launch(void* const* d_in, const int* in_sizes, int n_in,
                              void* d_out, int out_size)
{
    const float* m_st     = (const float*)d_in[0];
    const float* rbf      = (const float*)d_in[1];
    const float* cbf      = (const float*)d_in[2];
    const int*   idx_s    = (const int*)d_in[3];
    const int*   idx_swap = (const int*)d_in[4];
    const int*   basis    = (const int*)d_in[5];
    const float* W_m_rbf  = (const float*)d_in[6];
    const float* W_rbf    = (const float*)d_in[7];
    const float* W_m_cbf  = (const float*)d_in[8];
    const float* W_cbf    = (const float*)d_in[9];
    const float* W_dir    = (const float*)d_in[10];
    const float* W_st     = (const float*)d_in[11];
    const float* W_ts     = (const float*)d_in[12];
    float* out = (float*)d_out;

    const int E = in_sizes[0] / DEDGE;

    float *pR, *pT, *pXST, *pZ;
    __nv_bfloat16 *pmh, *pml, *prh, *prl, *pM1h, *pM1l, *pXh, *pXl, *pYh, *pYl;
    __nv_bfloat16 *wrbh, *wrbl, *wmrh, *wmrl, *wmch, *wmcl, *wdh, *wdl, *wsth, *wstl, *wtsh, *wtsl;
    cudaGetSymbolAddress((void**)&pR,   g_R);
    cudaGetSymbolAddress((void**)&pT,   g_T);
    cudaGetSymbolAddress((void**)&pXST, g_XST);
    cudaGetSymbolAddress((void**)&pZ,   g_Z);
    cudaGetSymbolAddress((void**)&pmh,  g_msth);  cudaGetSymbolAddress((void**)&pml, g_mstl);
    cudaGetSymbolAddress((void**)&prh,  g_rbfh);  cudaGetSymbolAddress((void**)&prl, g_rbfl);
    cudaGetSymbolAddress((void**)&pM1h, g_M1h);   cudaGetSymbolAddress((void**)&pM1l, g_M1l);
    cudaGetSymbolAddress((void**)&pXh,  g_Xh);    cudaGetSymbolAddress((void**)&pXl, g_Xl);
    cudaGetSymbolAddress((void**)&pYh,  g_Yh);    cudaGetSymbolAddress((void**)&pYl, g_Yl);
    cudaGetSymbolAddress((void**)&wrbh, g_Wrbh);  cudaGetSymbolAddress((void**)&wrbl, g_Wrbl);
    cudaGetSymbolAddress((void**)&wmrh, g_Wmrh);  cudaGetSymbolAddress((void**)&wmrl, g_Wmrl);
    cudaGetSymbolAddress((void**)&wmch, g_Wmch);  cudaGetSymbolAddress((void**)&wmcl, g_Wmcl);
    cudaGetSymbolAddress((void**)&wdh,  g_Wdh);   cudaGetSymbolAddress((void**)&wdl, g_Wdl);
    cudaGetSymbolAddress((void**)&wsth, g_Wsth);  cudaGetSymbolAddress((void**)&wstl, g_Wstl);
    cudaGetSymbolAddress((void**)&wtsh, g_Wtsh);  cudaGetSymbolAddress((void**)&wtsl, g_Wtsl);

    const int gB = (E + 127) / 128;

    // dynamic smem per variant: 2 stages * SSZ b16 * 2 B
    const int smem_n128 = 2 * (2 * 128 * 40 + 2 * 128 * 40) * 2;  // 81920
    const int smem_n64  = 2 * (2 * 128 * 40 + 2 * 64  * 40) * 2;  // 61440

    cudaFuncSetAttribute(gemm2<16, 128, EPI_NONE, OUT_F32>,
                         cudaFuncAttributeMaxDynamicSharedMemorySize, smem_n128);
    cudaFuncSetAttribute(gemm2<128, 128, EPI_SILU_MUL, OUT_BF16HL>,
                         cudaFuncAttributeMaxDynamicSharedMemorySize, smem_n128);
    cudaFuncSetAttribute(gemm2<128, 64, EPI_SILU, OUT_F32>,
                         cudaFuncAttributeMaxDynamicSharedMemorySize, smem_n64);
    cudaFuncSetAttribute(gemm2<64, 128, EPI_SILU, OUT_BF16HL>,
                         cudaFuncAttributeMaxDynamicSharedMemorySize, smem_n128);
    cudaFuncSetAttribute(gemm2<128, 128, EPI_SILU, OUT_F32>,
                         cudaFuncAttributeMaxDynamicSharedMemorySize, smem_n128);

    // ---- setup: split weights (transposed) + activations ----
    split_w_t<<<(16 * 128 + 255) / 256, 256>>>(W_rbf,   wrbh, wrbl, 16, 128);
    split_w_t<<<(128 * 128 + 255) / 256, 256>>>(W_m_rbf, wmrh, wmrl, 128, 128);
    split_w_t<<<(128 * 64 + 255) / 256, 256>>>(W_m_cbf, wmch, wmcl, 128, 64);
    split_w_t<<<(64 * 128 + 255) / 256, 256>>>(W_dir,   wdh, wdl, 64, 128);
    split_w_t<<<(128 * 128 + 255) / 256, 256>>>(W_st,   wsth, wstl, 128, 128);
    split_w_t<<<(128 * 128 + 255) / 256, 256>>>(W_ts,   wtsh, wtsl, 128, 128);
    split_rows<<<(E * 64 + 255) / 256, 256>>>(m_st, pmh, pml, E * 64);
    split_rows<<<(E * 8 + 255) / 256, 256>>>(rbf, prh, prl, E * 8);

    // K0: R = rbf @ W_rbf
    gemm2<16, 128, EPI_NONE, OUT_F32><<<gB, 256, smem_n128>>>(
        prh, prl, wrbh, wrbl, nullptr, pR, nullptr, nullptr, E);
    // K1: M1 = silu(m_st @ W_m_rbf) * R   -> bf16 hi/lo
    gemm2<128, 128, EPI_SILU_MUL, OUT_BF16HL><<<gB, 256, smem_n128>>>(
        pmh, pml, wmrh, wmrl, pR, nullptr, pM1h, pM1l, E);
    // K2: T = silu(M1 @ W_m_cbf)          -> fp32
    gemm2<128, 64, EPI_SILU, OUT_F32><<<gB, 256, smem_n64>>>(
        pM1h, pM1l, wmch, wmcl, nullptr, pT, nullptr, nullptr, E);
    // K3: triplet gather -> X bf16 hi/lo
    triplet_kernel<<<2048, 256>>>(pT, cbf, idx_s, basis, W_cbf, pXh, pXl, E);
    // K4: Y = silu(X @ W_dir)             -> bf16 hi/lo
    gemm2<64, 128, EPI_SILU, OUT_BF16HL><<<gB, 256, smem_n128>>>(
        pXh, pXl, wdh, wdl, nullptr, nullptr, pYh, pYl, E);
    // K5a: XST = silu(Y @ W_st)           -> fp32
    gemm2<128, 128, EPI_SILU, OUT_F32><<<gB, 256, smem_n128>>>(
        pYh, pYl, wsth, wstl, nullptr, pXST, nullptr, nullptr, E);
    // K5b: Z = silu(Y @ W_ts)             -> fp32
    gemm2<128, 128, EPI_SILU, OUT_F32><<<gB, 256, smem_n128>>>(
        pYh, pYl, wtsh, wtsl, nullptr, pZ, nullptr, nullptr, E);
    // K6: out = (XST + Z[idx_swap]) * INV_SQRT_2
    final_kernel<<<4096, 256>>>(pXST, pZ, idx_swap, out, E);
}